// round 17
// baseline (speedup 1.0000x reference)
#include <cuda_runtime.h>
#include <cuda_fp16.h>
#include <cstdint>
#include <math.h>

// Problem constants
#define B    4096
#define NF   64
#define KB   48
#define DE   64
#define F    4096
#define E    8
#define H    1024
#define O    512
#define T    2
#define TH   256

// ---------------- low-level helpers (plain sm_80+ PTX only) ----------------
__device__ __forceinline__ uint32_t smem_to_u32(const void* p) {
    uint32_t a;
    asm("{ .reg .u64 t; cvta.to.shared.u64 t, %1; cvt.u32.u64 %0, t; }" : "=r"(a) : "l"(p));
    return a;
}
__device__ __forceinline__ void cp_async16(uint32_t dst, const void* src, int src_bytes) {
    asm volatile("cp.async.cg.shared.global [%0], [%1], 16, %2;"
                 :: "r"(dst), "l"(src), "r"(src_bytes) : "memory");
}
#define CP_COMMIT() asm volatile("cp.async.commit_group;" ::: "memory")
#define CP_WAIT(n)  asm volatile("cp.async.wait_group %0;" :: "n"(n) : "memory")

__device__ __forceinline__ void ldsm_x4(uint32_t* r, uint32_t addr) {
    asm volatile("ldmatrix.sync.aligned.m8n8.x4.shared.b16 {%0,%1,%2,%3}, [%4];"
                 : "=r"(r[0]), "=r"(r[1]), "=r"(r[2]), "=r"(r[3]) : "r"(addr));
}
__device__ __forceinline__ void mma_f16(float* c, const uint32_t* a, const uint32_t* b) {
    asm volatile(
        "mma.sync.aligned.m16n8k16.row.col.f32.f16.f16.f32 "
        "{%0,%1,%2,%3}, {%4,%5,%6,%7}, {%8,%9}, {%0,%1,%2,%3};"
        : "+f"(c[0]), "+f"(c[1]), "+f"(c[2]), "+f"(c[3])
        : "r"(a[0]), "r"(a[1]), "r"(a[2]), "r"(a[3]), "r"(b[0]), "r"(b[1]));
}
__device__ __forceinline__ uint32_t pack_h2(float v0, float v1) {
    __half2 h = __halves2half2(__float2half_rn(v0), __float2half_rn(v1));
    return *(uint32_t*)&h;
}

// ---------------- device scratch ----------------
__device__ __half g_flat[(size_t)B * F];        // 32 MB (fp16 activations)
__device__ float  g_pl[(size_t)B * NF * E];     // 8 MB  per-(row,feature) gate partials
__device__ float  g_cw[(size_t)NF * KB * DE];   // 786 KB prefix sums (bias folded)
__device__ __half g_w1t[(size_t)E * H * F];     // 64 MB  [e][h][f]
__device__ __half g_w2t[(size_t)E * O * H];     // 8 MB   [e][o][h]
__device__ __half g_w3t[(size_t)T * TH * O];    // 512 KB [t][th][o]
__device__ __half g_h[(size_t)2 * B * H];       // 16 MB
__device__ float  g_eo[(size_t)2 * B * O];      // 16 MB
__device__ __half g_moe[(size_t)B * O];         // 4 MB
__device__ __half g_th[(size_t)T * B * TH];     // 4 MB
__device__ int   g_count[E];
__device__ int   g_base[E];
__device__ int   g_cursor[E];
__device__ int   g_tb[E + 1];
__device__ int   g_jobc;
__device__ int   g_te[B * 2];
__device__ float g_tg[B * 2];
__device__ int   g_rows[2 * B];
__device__ float g_gates[2 * B];
__device__ int   g_pair[B * 2];

// ---------------- prefix-sum embW via smem staging (+ count init) ----------------
// grid NF, block 256
__global__ __launch_bounds__(256) void k_cumw(
    const float* __restrict__ embW, const float* __restrict__ embb)
{
    __shared__ float w[KB * DE];    // 12 KB
    int n = blockIdx.x;
    int tid = threadIdx.x;
    if (n == 0 && tid < E) g_count[tid] = 0;
    for (int i = tid; i < KB * DE; i += 256)
        w[i] = embW[(size_t)n * KB * DE + i];
    __syncthreads();
    if (tid < DE) {
        float s = embb[n * DE + tid];
        #pragma unroll
        for (int k = 0; k < KB; k++) {
            g_cw[((size_t)n * KB + k) * DE + tid] = s;
            s += w[k * DE + tid];
        }
    }
}

// ---------------- weight transpose: W[e][k][n] -> T[e][n][k] fp16 ----------------
__global__ __launch_bounds__(256) void k_wsplit(
    const float* __restrict__ W, __half* __restrict__ Tw, int Kdim, int Ndim)
{
    __shared__ float t[32][33];
    int e = blockIdx.z;
    int kb = blockIdx.y * 32;
    int nb = blockIdx.x * 32;
    int tx = threadIdx.x, ty = threadIdx.y;
    const float* Wb = W + (size_t)e * Kdim * Ndim;
    #pragma unroll
    for (int i = ty; i < 32; i += 8)
        t[i][tx] = Wb[(size_t)(kb + i) * Ndim + nb + tx];
    __syncthreads();
    #pragma unroll
    for (int i = ty; i < 32; i += 8) {
        float v = t[tx][i];
        size_t o = ((size_t)e * Ndim + nb + i) * Kdim + kb + tx;
        Tw[o] = __float2half_rn(v);
    }
}

// ---------------- PLE via prefix-sum + ReLU -> flat fp16, + fused gate partials ----------------
__global__ __launch_bounds__(256) void k_ple(
    const float* __restrict__ x, const float* __restrict__ plew,
    const float* __restrict__ pleb, const float* __restrict__ embW,
    const float* __restrict__ gW)
{
    int n = blockIdx.x;
    int b0 = blockIdx.y * 64;
    int tid = threadIdx.x;

    __shared__ float wsh[KB], bsh[KB];
    __shared__ int   jr[64];
    __shared__ float fr[64];
    __shared__ float gwsh[DE][E];

    if (tid < KB) { wsh[tid] = plew[n * KB + tid]; bsh[tid] = pleb[n * KB + tid]; }
    for (int i = tid; i < DE * E; i += 256)
        ((float*)gwsh)[i] = gW[(size_t)(n * DE) * E + i];
    __syncthreads();

    if (tid < 64) {
        float xv = x[(b0 + tid) * NF + n];
        int j = 0;
        #pragma unroll
        for (int k = 0; k < KB; k++) {
            float enc = bsh[k] + wsh[k] * xv;
            j += (enc >= 1.f) ? 1 : 0;
        }
        if (j > KB - 1) j = KB - 1;
        float enc = bsh[j] + wsh[j] * xv;
        jr[tid] = j;
        fr[tid] = fmaxf(fminf(enc, 1.f), 0.f);
    }
    __syncthreads();

    int c0 = (tid & 15) * 4;
    int r0 = (tid >> 4) * 4;
    int lane = tid & 31;

    float v[4][4];
    #pragma unroll
    for (int r = 0; r < 4; r++) {
        int row = r0 + r;
        int j = jr[row];
        float f = fr[row];
        size_t base = ((size_t)n * KB + j) * DE + c0;
        float4 cw = *(const float4*)&g_cw[base];
        float4 w  = *(const float4*)&embW[base];
        v[r][0] = fmaxf(cw.x + f * w.x, 0.f);
        v[r][1] = fmaxf(cw.y + f * w.y, 0.f);
        v[r][2] = fmaxf(cw.z + f * w.z, 0.f);
        v[r][3] = fmaxf(cw.w + f * w.w, 0.f);
        size_t idx = (size_t)(b0 + row) * F + n * DE + c0;
        *(uint2*)&g_flat[idx] = make_uint2(pack_h2(v[r][0], v[r][1]),
                                           pack_h2(v[r][2], v[r][3]));
    }

    float p[4][E];
    #pragma unroll
    for (int r = 0; r < 4; r++)
        #pragma unroll
        for (int e = 0; e < E; e++) p[r][e] = 0.f;

    #pragma unroll
    for (int j = 0; j < 4; j++) {
        float gw[E];
        #pragma unroll
        for (int e = 0; e < E; e++) gw[e] = gwsh[c0 + j][e];
        #pragma unroll
        for (int r = 0; r < 4; r++)
            #pragma unroll
            for (int e = 0; e < E; e++)
                p[r][e] += v[r][j] * gw[e];
    }

    #pragma unroll
    for (int off = 8; off; off >>= 1)
        #pragma unroll
        for (int r = 0; r < 4; r++)
            #pragma unroll
            for (int e = 0; e < E; e++)
                p[r][e] += __shfl_xor_sync(0xffffffffu, p[r][e], off);

    if ((lane & 15) == 0) {
        #pragma unroll
        for (int r = 0; r < 4; r++) {
            int b = b0 + r0 + r;
            float* dst = &g_pl[((size_t)b * NF + n) * E];
            *(float4*)&dst[0] = make_float4(p[r][0], p[r][1], p[r][2], p[r][3]);
            *(float4*)&dst[4] = make_float4(p[r][4], p[r][5], p[r][6], p[r][7]);
        }
    }
}

// ---------------- gate reduce + top-2 ----------------
__global__ __launch_bounds__(256) void k_gate2(const float* __restrict__ gb)
{
    int b0 = blockIdx.x * 32;
    int tid = threadIdx.x;
    int r = tid >> 3;
    int e = tid & 7;
    int b = b0 + r;

    const float* p = &g_pl[((size_t)b * NF) * E + e];
    float s = 0.f;
    #pragma unroll
    for (int n = 0; n < NF; n++) s += p[n * E];
    s += gb[e];

    __shared__ float sl[32][E];
    sl[r][e] = s;
    __syncthreads();

    if (e == 0) {
        int i0 = 0;
        #pragma unroll
        for (int q = 1; q < E; q++) if (sl[r][q] > sl[r][i0]) i0 = q;
        int i1 = (i0 == 0) ? 1 : 0;
        #pragma unroll
        for (int q = 0; q < E; q++) if (q != i0 && sl[r][q] > sl[r][i1]) i1 = q;
        float e1 = __expf(sl[r][i1] - sl[r][i0]);
        float inv = 1.f / (1.f + e1);
        g_te[b * 2 + 0] = i0;  g_tg[b * 2 + 0] = inv;
        g_te[b * 2 + 1] = i1;  g_tg[b * 2 + 1] = e1 * inv;
        atomicAdd(&g_count[i0], 1);
        atomicAdd(&g_count[i1], 1);
    }
}

__global__ void k_scan() {
    if (threadIdx.x == 0) {
        int s = 0, tb = 0;
        for (int e = 0; e < E; e++) {
            g_base[e] = s; g_cursor[e] = s; s += g_count[e];
            g_tb[e] = tb; tb += (g_count[e] + 127) / 128;
        }
        g_tb[E] = tb;
        g_jobc = 0;
    }
}

__global__ __launch_bounds__(256) void k_assign() {
    int b = blockIdx.x * 256 + threadIdx.x;
    if (b >= B) return;
    #pragma unroll
    for (int j = 0; j < 2; j++) {
        int e = g_te[b * 2 + j];
        int slot = atomicAdd(&g_cursor[e], 1);
        g_rows[slot]  = b;
        g_gates[slot] = g_tg[b * 2 + j];
        g_pair[b * 2 + j] = slot;
    }
}

// ---------------- moe combine: eo pairs -> fp16 moe[B][O] ----------------
__global__ __launch_bounds__(256) void k_moe()
{
    int b = blockIdx.x * 4 + (threadIdx.x >> 6);
    int c = (threadIdx.x & 63) * 8;
    int s0 = g_pair[b * 2 + 0], s1 = g_pair[b * 2 + 1];
    const float* e0 = &g_eo[(size_t)s0 * O + c];
    const float* e1 = &g_eo[(size_t)s1 * O + c];
    float4 a0 = *(const float4*)&e0[0], a1 = *(const float4*)&e0[4];
    float4 b0 = *(const float4*)&e1[0], b1 = *(const float4*)&e1[4];
    uint4 outv;
    outv.x = pack_h2(a0.x + b0.x, a0.y + b0.y);
    outv.y = pack_h2(a0.z + b0.z, a0.w + b0.w);
    outv.z = pack_h2(a1.x + b1.x, a1.y + b1.y);
    outv.w = pack_h2(a1.z + b1.z, a1.w + b1.w);
    *(uint4*)&g_moe[(size_t)b * O + c] = outv;
}

// ---------------- GEMM common pieces ----------------
#define GBM 128
#define GKT 64
#define STG_BYTES 32768u
#define OFF_B_C   16384u

// Persistent GEMM1: gathered rows, relu fp16 out. grid = 2 x nSM.
__global__ __launch_bounds__(256, 2) void k_gemm1_p(
    const __half* __restrict__ A, const __half* __restrict__ Wt,
    const float* __restrict__ bias)
{
    extern __shared__ char smem[];
    uint32_t sb = smem_to_u32(smem);
    __shared__ int rows_s[GBM];
    __shared__ int s_job;

    const int NT_N = H / 128;   // 8
    int tid = threadIdx.x;
    int lane = tid & 31, wid = tid >> 5;

    // job-invariant mappings
    int lrow = tid >> 1;
    int lcb  = (tid & 1) * 4;
    uint32_t lsw = (uint32_t)((lrow & 7) << 4);
    uint32_t lbase = (uint32_t)(lrow * 128);
    int wm = wid >> 2;
    int wn = wid & 3;
    int a_row = wm * 64 + (lane & 15);
    uint32_t a_c  = (uint32_t)((lane >> 4) * 16);
    uint32_t asw  = (uint32_t)((a_row & 7) << 4);
    int b_row = wn * 32 + (lane & 7) + ((lane >> 4) << 3);
    uint32_t b_c  = (uint32_t)(((lane >> 3) & 1) * 16);
    uint32_t bsw  = (uint32_t)((b_row & 7) << 4);

    while (true) {
        __syncthreads();
        if (tid == 0) s_job = atomicAdd(&g_jobc, 1);
        __syncthreads();
        int job = s_job;
        int mt_total = g_tb[E];
        if (job >= mt_total * NT_N) return;

        int mt = job / NT_N;
        int nt = job - mt * NT_N;
        int e = 0;
        while (e < E - 1 && mt >= g_tb[e + 1]) e++;
        int m0 = (mt - g_tb[e]) * GBM;
        int cnt = g_count[e];
        int base = g_base[e];
        int n0 = nt * 128;

        if (tid < GBM) {
            int m = m0 + tid;
            rows_s[tid] = (m < cnt) ? g_rows[base + m] : -1;
        }
        __syncthreads();

        int gr = rows_s[lrow];
        int abytes = (gr >= 0) ? 16 : 0;
        const __half* arow = A + (size_t)((gr >= 0) ? gr : 0) * F;
        const __half* brow = Wt + ((size_t)e * H + n0 + lrow) * F;

        float acc[4][4][4];
        #pragma unroll
        for (int i = 0; i < 4; i++)
            #pragma unroll
            for (int j = 0; j < 4; j++)
                #pragma unroll
                for (int q = 0; q < 4; q++) acc[i][j][q] = 0.f;

        const int NT = F / GKT;

        #define LOAD_STAGE(stg_, kt_) do {                                       \
            uint32_t s_ = sb + (uint32_t)(stg_) * STG_BYTES;                      \
            int k0_ = (kt_) * GKT;                                                \
            _Pragma("unroll")                                                     \
            for (int q = 0; q < 4; q++) {                                         \
                int ch = lcb + q;                                                 \
                uint32_t so = lbase + (((uint32_t)(ch * 16)) ^ lsw);              \
                cp_async16(s_ + so, arow + k0_ + ch * 8, abytes);                 \
                cp_async16(s_ + OFF_B_C + so, brow + k0_ + ch * 8, 16);           \
            }                                                                     \
            CP_COMMIT();                                                          \
        } while (0)

        LOAD_STAGE(0, 0);
        LOAD_STAGE(1, 1);

        int stg = 0;
        for (int kt = 0; kt < NT; kt++) {
            if (kt + 2 < NT) {
                int ns = stg + 2; if (ns >= 3) ns -= 3;
                LOAD_STAGE(ns, kt + 2);
                CP_WAIT(2);
            } else if (kt + 1 < NT) {
                CP_WAIT(1);
            } else {
                CP_WAIT(0);
            }
            __syncthreads();

            uint32_t s0 = sb + (uint32_t)stg * STG_BYTES;
            #pragma unroll
            for (int kk = 0; kk < 4; kk++) {
                uint32_t ah[4][4], bh[2][4];
                #pragma unroll
                for (int i = 0; i < 4; i++) {
                    uint32_t ro = (uint32_t)((a_row + i * 16) * 128);
                    ldsm_x4(ah[i], s0 + ro + ((a_c + kk * 32) ^ asw));
                }
                #pragma unroll
                for (int p = 0; p < 2; p++) {
                    uint32_t ro = (uint32_t)((b_row + p * 16) * 128);
                    ldsm_x4(bh[p], s0 + OFF_B_C + ro + ((b_c + kk * 32) ^ bsw));
                }
                #pragma unroll
                for (int i = 0; i < 4; i++)
                    #pragma unroll
                    for (int j = 0; j < 4; j++) {
                        const uint32_t* bj = &bh[j >> 1][(j & 1) * 2];
                        mma_f16(acc[i][j], ah[i], bj);
                    }
            }
            __syncthreads();
            stg = (stg == 2) ? 0 : stg + 1;
        }
        #undef LOAD_STAGE

        int g = lane >> 2;
        int cg = (lane & 3) * 2;
        #pragma unroll
        for (int i = 0; i < 4; i++) {
            #pragma unroll
            for (int half = 0; half < 2; half++) {
                int m = m0 + wm * 64 + i * 16 + g + half * 8;
                if (m < cnt) {
                    int slot = base + m;
                    #pragma unroll
                    for (int j = 0; j < 4; j++) {
                        int col = n0 + wn * 32 + j * 8 + cg;
                        float v0 = fmaxf(acc[i][j][half * 2 + 0] + bias[(size_t)e * H + col], 0.f);
                        float v1 = fmaxf(acc[i][j][half * 2 + 1] + bias[(size_t)e * H + col + 1], 0.f);
                        *(uint32_t*)&g_h[(size_t)slot * H + col] = pack_h2(v0, v1);
                    }
                }
            }
        }
    }
}

// Non-persistent template for GEMM2 (MODE 1) and tower (MODE 2).
template<int KTOT, int NTOT, int MODE>
__global__ __launch_bounds__(256, 2) void k_mma_gemm(
    const __half* __restrict__ A, const __half* __restrict__ Wt,
    const float* __restrict__ bias)
{
    int e = blockIdx.z;
    int cnt = (MODE == 2) ? B : g_count[e];
    int m0 = blockIdx.y * GBM;
    if (m0 >= cnt) return;
    int base = (MODE == 2) ? 0 : g_base[e];
    int n0 = blockIdx.x * 128;

    extern __shared__ char smem[];
    uint32_t sb = smem_to_u32(smem);

    int tid = threadIdx.x;
    int lane = tid & 31, wid = tid >> 5;

    int lrow = tid >> 1;
    int lcb  = (tid & 1) * 4;
    int m = m0 + lrow;
    int abytes = (m < cnt) ? 16 : 0;
    size_t r = (m < cnt) ? (size_t)(base + m) : 0;
    const __half* arow = A + r * KTOT;
    const __half* brow = Wt + ((size_t)e * NTOT + n0 + lrow) * KTOT;
    uint32_t lsw = (uint32_t)((lrow & 7) << 4);
    uint32_t lbase = (uint32_t)(lrow * 128);

    int wm = wid >> 2;
    int wn = wid & 3;
    int a_row = wm * 64 + (lane & 15);
    uint32_t a_c  = (uint32_t)((lane >> 4) * 16);
    uint32_t asw  = (uint32_t)((a_row & 7) << 4);
    int b_row = wn * 32 + (lane & 7) + ((lane >> 4) << 3);
    uint32_t b_c  = (uint32_t)(((lane >> 3) & 1) * 16);
    uint32_t bsw  = (uint32_t)((b_row & 7) << 4);

    float acc[4][4][4];
    #pragma unroll
    for (int i = 0; i < 4; i++)
        #pragma unroll
        for (int j = 0; j < 4; j++)
            #pragma unroll
            for (int q = 0; q < 4; q++) acc[i][j][q] = 0.f;

    const int NT = KTOT / GKT;

    #define LOAD_STAGE(stg_, kt_) do {                                           \
        uint32_t s_ = sb + (uint32_t)(stg_) * STG_BYTES;                          \
        int k0_ = (kt_) * GKT;                                                    \
        _Pragma("unroll")                                                         \
        for (int q = 0; q < 4; q++) {                                             \
            int ch = lcb + q;                                                     \
            uint32_t so = lbase + (((uint32_t)(ch * 16)) ^ lsw);                  \
            cp_async16(s_ + so, arow + k0_ + ch * 8, abytes);                     \
            cp_async16(s_ + OFF_B_C + so, brow + k0_ + ch * 8, 16);               \
        }                                                                         \
        CP_COMMIT();                                                              \
    } while (0)

    LOAD_STAGE(0, 0);
    if (NT > 1) LOAD_STAGE(1, 1);

    int stg = 0;
    for (int kt = 0; kt < NT; kt++) {
        if (kt + 2 < NT) {
            int ns = stg + 2; if (ns >= 3) ns -= 3;
            LOAD_STAGE(ns, kt + 2);
            CP_WAIT(2);
        } else if (kt + 1 < NT) {
            CP_WAIT(1);
        } else {
            CP_WAIT(0);
        }
        __syncthreads();

        uint32_t s0 = sb + (uint32_t)stg * STG_BYTES;
        #pragma unroll
        for (int kk = 0; kk < 4; kk++) {
            uint32_t ah[4][4], bh[2][4];
            #pragma unroll
            for (int i = 0; i < 4; i++) {
                uint32_t ro = (uint32_t)((a_row + i * 16) * 128);
                ldsm_x4(ah[i], s0 + ro + ((a_c + kk * 32) ^ asw));
            }
            #pragma unroll
            for (int p = 0; p < 2; p++) {
                uint32_t ro = (uint32_t)((b_row + p * 16) * 128);
                ldsm_x4(bh[p], s0 + OFF_B_C + ro + ((b_c + kk * 32) ^ bsw));
            }
            #pragma unroll
            for (int i = 0; i < 4; i++)
                #pragma unroll
                for (int j = 0; j < 4; j++) {
                    const uint32_t* bj = &bh[j >> 1][(j & 1) * 2];
                    mma_f16(acc[i][j], ah[i], bj);
                }
        }
        __syncthreads();
        stg = (stg == 2) ? 0 : stg + 1;
    }
    #undef LOAD_STAGE

    int g = lane >> 2;
    int cg = (lane & 3) * 2;
    #pragma unroll
    for (int i = 0; i < 4; i++) {
        #pragma unroll
        for (int half = 0; half < 2; half++) {
            int mm = m0 + wm * 64 + i * 16 + g + half * 8;
            if (mm < cnt) {
                int slot = base + mm;
                float gate = (MODE == 1) ? g_gates[slot] : 0.f;
                #pragma unroll
                for (int j = 0; j < 4; j++) {
                    int col = n0 + wn * 32 + j * 8 + cg;
                    float bv0 = bias[(size_t)e * NTOT + col];
                    float bv1 = bias[(size_t)e * NTOT + col + 1];
                    float v0 = acc[i][j][half * 2 + 0] + bv0;
                    float v1 = acc[i][j][half * 2 + 1] + bv1;
                    if (MODE == 1) {
                        float2 v = make_float2(gate * v0, gate * v1);
                        *(float2*)&g_eo[(size_t)slot * O + col] = v;
                    } else {
                        v0 = fmaxf(v0, 0.f); v1 = fmaxf(v1, 0.f);
                        *(uint32_t*)&g_th[(size_t)e * B * NTOT + (size_t)mm * NTOT + col]
                            = pack_h2(v0, v1);
                    }
                }
            }
        }
    }
}

// ---------------- tower final ----------------
__global__ __launch_bounds__(256) void k_tower2(
    const float* __restrict__ tw2, const float* __restrict__ tb2,
    float* __restrict__ out)
{
    int tid = threadIdx.x;
    int lane = tid & 31, wid = tid >> 5;
    int idx = blockIdx.x * 8 + wid;
    int b = idx >> 1;
    int t = idx & 1;

    const __half* th = &g_th[(size_t)t * B * TH + (size_t)b * TH + lane * 8];
    uint4 hv = *(const uint4*)th;
    const float* w = &tw2[t * TH + lane * 8];
    float4 w0 = *(const float4*)&w[0], w1 = *(const float4*)&w[4];

    __half2 h01 = *(__half2*)&hv.x, h23 = *(__half2*)&hv.y;
    __half2 h45 = *(__half2*)&hv.z, h67 = *(__half2*)&hv.w;
    float s = __half2float(__low2half(h01)) * w0.x
            + __half2float(__high2half(h01)) * w0.y
            + __half2float(__low2half(h23)) * w0.z
            + __half2float(__high2half(h23)) * w0.w
            + __half2float(__low2half(h45)) * w1.x
            + __half2float(__high2half(h45)) * w1.y
            + __half2float(__low2half(h67)) * w1.z
            + __half2float(__high2half(h67)) * w1.w;
    #pragma unroll
    for (int off = 16; off; off >>= 1)
        s += __shfl_down_sync(0xffffffffu, s, off);
    if (lane == 0) out[b * T + t] = s + tb2[t];
}

// ---------------- launch ----------------
extern "C" void kernel_launch(void* const* d_in, const int* in_sizes, int n_in,
                              void* d_out, int out_size)
{
    const float* x     = (const float*)d_in[0];
    const float* plew  = (const float*)d_in[1];
    const float* pleb  = (const float*)d_in[2];
    const float* embW  = (const float*)d_in[3];
    const float* embb  = (const float*)d_in[4];
    const float* gW    = (const float*)d_in[5];
    const float* gb    = (const float*)d_in[6];
    const float* eW1   = (const float*)d_in[7];
    const float* eb1   = (const float*)d_in[8];
    const float* eW2   = (const float*)d_in[9];
    const float* eb2   = (const float*)d_in[10];
    const float* tw1   = (const float*)d_in[11];
    const float* tb1   = (const float*)d_in[12];
    const float* tw2   = (const float*)d_in[13];
    const float* tb2   = (const float*)d_in[14];
    float* out = (float*)d_out;

    const int SMEM_BYTES = 3 * (int)STG_BYTES;   // 98304
    static cudaStream_t s2 = nullptr;
    static cudaEvent_t ev_fork = nullptr, ev_join = nullptr;
    static int nsm = 148;
    if (!s2) {
        cudaDeviceGetAttribute(&nsm, cudaDevAttrMultiProcessorCount, 0);
        if (nsm <= 0) nsm = 148;
        cudaFuncSetAttribute(k_gemm1_p, cudaFuncAttributeMaxDynamicSharedMemorySize, SMEM_BYTES);
        cudaFuncSetAttribute(k_mma_gemm<H, O, 1>, cudaFuncAttributeMaxDynamicSharedMemorySize, SMEM_BYTES);
        cudaFuncSetAttribute(k_mma_gemm<O, TH, 2>, cudaFuncAttributeMaxDynamicSharedMemorySize, SMEM_BYTES);
        cudaStreamCreateWithFlags(&s2, cudaStreamNonBlocking);
        cudaEventCreateWithFlags(&ev_fork, cudaEventDisableTiming);
        cudaEventCreateWithFlags(&ev_join, cudaEventDisableTiming);
    }

    __half *w1t, *w2t, *w3t, *flat, *h_buf, *moe;
    cudaGetSymbolAddress((void**)&w1t, g_w1t);
    cudaGetSymbolAddress((void**)&w2t, g_w2t);
    cudaGetSymbolAddress((void**)&w3t, g_w3t);
    cudaGetSymbolAddress((void**)&flat, g_flat);
    cudaGetSymbolAddress((void**)&h_buf, g_h);
    cudaGetSymbolAddress((void**)&moe, g_moe);

    // fork: weight conversion runs concurrently with PLE->gate->assign
    cudaEventRecord(ev_fork, 0);
    cudaStreamWaitEvent(s2, ev_fork, 0);
    k_wsplit<<<dim3(H / 32, F / 32, E), dim3(32, 8), 0, s2>>>(eW1, w1t, F, H);
    k_wsplit<<<dim3(O / 32, H / 32, E), dim3(32, 8), 0, s2>>>(eW2, w2t, H, O);
    k_wsplit<<<dim3(TH / 32, O / 32, T), dim3(32, 8), 0, s2>>>(tw1, w3t, O, TH);
    cudaEventRecord(ev_join, s2);

    k_cumw<<<NF, 256>>>(embW, embb);
    k_ple<<<dim3(NF, B / 64), 256>>>(x, plew, pleb, embW, gW);
    k_gate2<<<B / 32, 256>>>(gb);
    k_scan<<<1, 32>>>();
    k_assign<<<(B + 255) / 256, 256>>>();

    // join before GEMM1 consumes weights
    cudaStreamWaitEvent(0, ev_join, 0);

    k_gemm1_p<<<2 * nsm, 256, SMEM_BYTES>>>(flat, w1t, eb1);
    k_mma_gemm<H, O, 1><<<dim3(O / 128, B / GBM, E), 256, SMEM_BYTES>>>(h_buf, w2t, eb2);
    k_moe<<<B / 4, 256>>>();
    k_mma_gemm<O, TH, 2><<<dim3(TH / 128, B / GBM, T), 256, SMEM_BYTES>>>(moe, w3t, tb1);
    k_tower2<<<B / 4, 256>>>(tw2, tb2, out);
}